// round 15
// baseline (speedup 1.0000x reference)
#include <cuda_runtime.h>
#include <cuda_fp16.h>
#include <cstdint>

#define BATCH   16384
#define FEAT    512
#define NODES   4095
#define NPAD    4096
#define SPLIT   511            // nodes < SPLIT (levels 0-8) stored fp32

#define BM 128
#define BN 128
#define BKH 64                 // halves per k-stage (128B rows)
#define NKSTAGE (FEAT / BKH)   // 8
#define PSTAGES 3

#define NCHUNKS  4
#define CROWS    (BATCH / NCHUNKS)     // 4096 rows per chunk

// smem: A stages [0,48K), B stages [48K,96K), bias*scale 96K, scale 96K+512
#define SMA(s)   ((s) * 16384)
#define SMB(s)   (49152 + (s) * 16384)
#define SM_BS    98304
#define SM_SCALE 98816
#define SM_TOTAL 99328

__device__ float  g_P32[(size_t)512 * BATCH];        // levels 0-8  (nodes 0..510)
__device__ __half g_P16[(size_t)NPAD * BATCH];       // levels 9-11 (nodes 511..4094)
__device__ __half g_Xh[(size_t)BATCH * FEAT];
__device__ __half g_Wh[(size_t)NPAD * FEAT];         // row 4095 zeroed

// sigmoid via MUFU approx: rcp(1 + ex2(-x*log2e)); err ~2^-22
__device__ __forceinline__ float fast_sigmoid(float x) {
    float e, r;
    asm("ex2.approx.f32 %0, %1;" : "=f"(e) : "f"(-1.4426950408889634f * x));
    asm("rcp.approx.f32 %0, %1;" : "=f"(r) : "f"(1.0f + e));
    return r;
}
__device__ __forceinline__ uint32_t smem_u32(const void* p) {
    return (uint32_t)__cvta_generic_to_shared(p);
}
__device__ __forceinline__ void cp16(uint32_t dst, const void* src) {
    asm volatile("cp.async.cg.shared.global [%0], [%1], 16;" :: "r"(dst), "l"(src));
}
__device__ __forceinline__ void cp_commit() {
    asm volatile("cp.async.commit_group;" ::: "memory");
}
__device__ __forceinline__ void cp_wait1() {
    asm volatile("cp.async.wait_group 1;" ::: "memory");
}
__device__ __forceinline__ void ldsm4(uint32_t& r0, uint32_t& r1, uint32_t& r2,
                                      uint32_t& r3, uint32_t a) {
    asm volatile("ldmatrix.sync.aligned.m8n8.x4.shared.b16 {%0,%1,%2,%3}, [%4];"
                 : "=r"(r0), "=r"(r1), "=r"(r2), "=r"(r3) : "r"(a));
}
__device__ __forceinline__ void mma_f16(float* c, const uint32_t* a, const uint32_t* b) {
    asm volatile(
        "mma.sync.aligned.m16n8k16.row.col.f32.f16.f16.f32 "
        "{%0,%1,%2,%3}, {%4,%5,%6,%7}, {%8,%9}, {%0,%1,%2,%3};"
        : "+f"(c[0]), "+f"(c[1]), "+f"(c[2]), "+f"(c[3])
        : "r"(a[0]), "r"(a[1]), "r"(a[2]), "r"(a[3]), "r"(b[0]), "r"(b[1]));
}

// ---------------------------------------------------------------------------
// Fused prep: convert X (blocks [0,8192)) and W (blocks [8192,10240))
// ---------------------------------------------------------------------------
__global__ __launch_bounds__(256)
void prep(const float* __restrict__ X, const float* __restrict__ W)
{
    const int bid = blockIdx.x;
    if (bid < 8192) {
        size_t i = (size_t)bid * 256 + threadIdx.x;
        float4 v = ((const float4*)X)[i];
        __half2* d = (__half2*)g_Xh;
        d[2 * i]     = __floats2half2_rn(v.x, v.y);
        d[2 * i + 1] = __floats2half2_rn(v.z, v.w);
    } else {
        size_t i = (size_t)(bid - 8192) * 256 + threadIdx.x;
        __half2* d = (__half2*)g_Wh;
        if (i < (size_t)NODES * FEAT / 4) {
            float4 v = ((const float4*)W)[i];
            d[2 * i]     = __floats2half2_rn(v.x, v.y);
            d[2 * i + 1] = __floats2half2_rn(v.z, v.w);
        } else {
            d[2 * i]     = __floats2half2_rn(0.f, 0.f);
            d[2 * i + 1] = __floats2half2_rn(0.f, 0.f);
        }
    }
}

// ---------------------------------------------------------------------------
// Kernel 1: fp16 mma.sync GEMM — R4/R10 config (measured best), two barriers
// per k-stage. Processes CROWS rows starting at m0base.
// ---------------------------------------------------------------------------
__global__ __launch_bounds__(256, 2)
void gemm_mma(const float* __restrict__ bias, const float* __restrict__ scale,
              int m0base)
{
    extern __shared__ char smem[];
    const uint32_t sbase = smem_u32(smem);

    const int tid  = threadIdx.x;
    const int lane = tid & 31;
    const int wid  = tid >> 5;
    const int warpM = wid & 1;          // 2 x 64 rows
    const int warpN = wid >> 1;         // 4 x 32 cols
    const int m0 = m0base + blockIdx.y * BM;
    const int n0 = blockIdx.x * BN;

    float* sbs = (float*)(smem + SM_BS);     // bias*scale
    float* ss  = (float*)(smem + SM_SCALE);  // scale
    if (tid < BN) {
        int nn = n0 + tid;
        bool v = nn < NODES;
        float bb = v ? bias[nn] : 0.f;
        float sc = v ? scale[nn] : 1.f;
        sbs[tid] = bb * sc;
        ss[tid]  = sc;
    }

    auto issue_stage = [&](int kt) {
        const int s = kt % PSTAGES;
        const int kb = kt * BKH;
        #pragma unroll
        for (int i = 0; i < 4; ++i) {
            int c = tid + i * 256;
            int row = c >> 3, chk = c & 7;
            uint32_t coff = (uint32_t)(chk * 16) ^ ((row & 7) << 4);
            cp16(sbase + SMA(s) + row * 128 + coff,
                 g_Xh + (size_t)(m0 + row) * FEAT + kb + chk * 8);
        }
        #pragma unroll
        for (int i = 0; i < 4; ++i) {
            int c = tid + i * 256;
            int row = c >> 3, chk = c & 7;
            uint32_t coff = (uint32_t)(chk * 16) ^ ((row & 7) << 4);
            cp16(sbase + SMB(s) + row * 128 + coff,
                 g_Wh + (size_t)(n0 + row) * FEAT + kb + chk * 8);
        }
        cp_commit();
    };

    float acc[4][4][4];
    #pragma unroll
    for (int f = 0; f < 4; f++)
        #pragma unroll
        for (int g = 0; g < 4; g++)
            #pragma unroll
            for (int j = 0; j < 4; j++)
                acc[f][g][j] = 0.f;

    issue_stage(0);
    issue_stage(1);

    const int q  = lane >> 3;
    const int lr = lane & 7;

    for (int kt = 0; kt < NKSTAGE; ++kt) {
        cp_wait1();
        __syncthreads();
        if (kt + 2 < NKSTAGE) issue_stage(kt + 2);
        else cp_commit();

        const uint32_t abase = sbase + SMA(kt % PSTAGES);
        const uint32_t bbase = sbase + SMB(kt % PSTAGES);

        #pragma unroll
        for (int g = 0; g < 4; ++g) {
            uint32_t af[4][4];
            #pragma unroll
            for (int t = 0; t < 4; ++t) {
                int trow = warpM * 64 + t * 16 + lr + (q & 1) * 8;
                uint32_t kbyte = (uint32_t)(g * 32 + (q >> 1) * 16);
                uint32_t addr = abase + trow * 128 + (kbyte ^ ((trow & 7) << 4));
                ldsm4(af[t][0], af[t][1], af[t][2], af[t][3], addr);
            }
            uint32_t bf[2][4];
            #pragma unroll
            for (int t = 0; t < 2; ++t) {
                int nrow = warpN * 32 + t * 16 + lr + (q >> 1) * 8;
                uint32_t kbyte = (uint32_t)(g * 32 + (q & 1) * 16);
                uint32_t addr = bbase + nrow * 128 + (kbyte ^ ((nrow & 7) << 4));
                ldsm4(bf[t][0], bf[t][1], bf[t][2], bf[t][3], addr);
            }
            #pragma unroll
            for (int f = 0; f < 4; ++f)
                #pragma unroll
                for (int gg = 0; gg < 4; ++gg) {
                    uint32_t bb[2] = { bf[gg >> 1][(gg & 1) * 2],
                                       bf[gg >> 1][(gg & 1) * 2 + 1] };
                    mma_f16(acc[f][gg], af[f], bb);
                }
        }
        __syncthreads();
    }

    // Epilogue: sigmoid(acc*s + b*s), direct hybrid stores
    const int rbase = m0 + warpM * 64 + (lane >> 2);
    #pragma unroll
    for (int f = 0; f < 4; ++f) {
        #pragma unroll
        for (int g = 0; g < 4; ++g) {
            const int cidx = warpN * 32 + g * 8 + (lane & 3) * 2;
            const int m = rbase + f * 16;
            #pragma unroll
            for (int j = 0; j < 4; ++j) {
                const int col = cidx + (j & 1);
                const int mm  = m + ((j >> 1) ? 8 : 0);
                const int node = n0 + col;
                float p = fast_sigmoid(fmaf(acc[f][g][j], ss[col], sbs[col]));
                if (node < SPLIT)
                    g_P32[(size_t)node * BATCH + mm] = p;
                else
                    g_P16[(size_t)node * BATCH + mm] = __float2half_rn(p);
            }
        }
    }
}

// ---------------------------------------------------------------------------
// Kernel 2: tree walk — R6 shape (512 thr = 16 segs x 32 lanes, 32 groups/seg)
// on a chunk of rows starting at row-pair rh0.
// ---------------------------------------------------------------------------
__global__ __launch_bounds__(512)
void tree_kernel(const float* __restrict__ leaves, float* __restrict__ out,
                 int rh0)
{
    __shared__ float sl[4096];
    __shared__ float2 part[16][33];
    const int tid = threadIdx.x;

    for (int i = tid; i < 4096; i += 512)
        sl[i] = fast_sigmoid(leaves[i]);
    __syncthreads();

    const int lane = tid & 31;
    const int seg  = tid >> 5;                       // 0..15
    const int rhb  = rh0 + blockIdx.x * 32;          // block's row-pair base
    const int rh   = rhb + lane;
    const float2*  __restrict__ PT2 = (const float2*)g_P32;
    const __half2* __restrict__ PH2 = (const __half2*)g_P16;
    const int HB = BATCH / 2;                        // 8192

    const int g0 = seg * 32;

    float prefA0 = 1.f, prefB0 = 1.f;
    #pragma unroll
    for (int d = 0; d < 4; ++d) {
        int idx = (1 << d) - 1 + (g0 >> (9 - d));
        float2 p = PT2[idx * HB + rh];
        int b = (g0 >> (8 - d)) & 1;
        prefA0 = b ? (prefA0 - prefA0 * p.x) : (prefA0 * p.x);
        prefB0 = b ? (prefB0 - prefB0 * p.y) : (prefB0 * p.y);
    }
    const float2 p4 = PT2[(15 + (g0 >> 5)) * HB + rh];

    float accA = 0.f, accB = 0.f;
    #pragma unroll 2
    for (int gi = 0; gi < 32; ++gi) {
        const int g = g0 + gi;
        const int b4 = (g >> 4) & 1;
        float prefA = b4 ? (prefA0 - prefA0 * p4.x) : (prefA0 * p4.x);
        float prefB = b4 ? (prefB0 - prefB0 * p4.y) : (prefB0 * p4.y);
        #pragma unroll
        for (int d = 5; d < 9; ++d) {
            int idx = (1 << d) - 1 + (g >> (9 - d));
            float2 p = PT2[idx * HB + rh];
            int b = (g >> (8 - d)) & 1;
            prefA = b ? (prefA - prefA * p.x) : (prefA * p.x);
            prefB = b ? (prefB - prefB * p.y) : (prefB * p.y);
        }
        float2 p9  = __half22float2(PH2[(511  + g)     * HB + rh]);
        float2 pa0 = __half22float2(PH2[(1023 + 2 * g) * HB + rh]);
        float2 pa1 = __half22float2(PH2[(1024 + 2 * g) * HB + rh]);
        float2 pb0 = __half22float2(PH2[(2047 + 4 * g) * HB + rh]);
        float2 pb1 = __half22float2(PH2[(2048 + 4 * g) * HB + rh]);
        float2 pb2 = __half22float2(PH2[(2049 + 4 * g) * HB + rh]);
        float2 pb3 = __half22float2(PH2[(2050 + 4 * g) * HB + rh]);

        const float* s8 = &sl[g * 8];
        {
            float u0 = prefA * p9.x, u1 = prefA - u0;
            float v0 = u0 * pa0.x,   v1 = u0 - v0;
            float v2 = u1 * pa1.x,   v3 = u1 - v2;
            float w0 = v0 * pb0.x,   w1 = v0 - w0;
            float w2 = v1 * pb1.x,   w3 = v1 - w2;
            float w4 = v2 * pb2.x,   w5 = v2 - w4;
            float w6 = v3 * pb3.x,   w7 = v3 - w6;
            accA += s8[0] * w0 + s8[1] * w1 + s8[2] * w2 + s8[3] * w3
                  + s8[4] * w4 + s8[5] * w5 + s8[6] * w6 + s8[7] * w7;
        }
        {
            float u0 = prefB * p9.y, u1 = prefB - u0;
            float v0 = u0 * pa0.y,   v1 = u0 - v0;
            float v2 = u1 * pa1.y,   v3 = u1 - v2;
            float w0 = v0 * pb0.y,   w1 = v0 - w0;
            float w2 = v1 * pb1.y,   w3 = v1 - w2;
            float w4 = v2 * pb2.y,   w5 = v2 - w4;
            float w6 = v3 * pb3.y,   w7 = v3 - w6;
            accB += s8[0] * w0 + s8[1] * w1 + s8[2] * w2 + s8[3] * w3
                  + s8[4] * w4 + s8[5] * w5 + s8[6] * w6 + s8[7] * w7;
        }
    }
    part[seg][lane] = make_float2(accA, accB);
    __syncthreads();
    if (tid < 32) {
        float tA = 0.f, tB = 0.f;
        #pragma unroll
        for (int s2 = 0; s2 < 16; ++s2) {
            float2 v = part[s2][tid];
            tA += v.x; tB += v.y;
        }
        const int base = (rhb + tid) * 2;
        out[base]     = tA;
        out[base + 1] = tB;
    }
}

// ---------------------------------------------------------------------------
extern "C" void kernel_launch(void* const* d_in, const int* in_sizes, int n_in,
                              void* d_out, int out_size)
{
    const float* X      = (const float*)d_in[0];
    const float* W      = (const float*)d_in[1];
    const float* b      = (const float*)d_in[2];
    const float* s      = (const float*)d_in[3];
    const float* leaves = (const float*)d_in[4];
    float* out = (float*)d_out;

    static bool init = false;
    static cudaStream_t s2;
    static cudaEvent_t eg[NCHUNKS], ejoin;
    if (!init) {
        cudaFuncSetAttribute(gemm_mma, cudaFuncAttributeMaxDynamicSharedMemorySize,
                             SM_TOTAL);
        cudaStreamCreateWithFlags(&s2, cudaStreamNonBlocking);
        for (int k = 0; k < NCHUNKS; ++k)
            cudaEventCreateWithFlags(&eg[k], cudaEventDisableTiming);
        cudaEventCreateWithFlags(&ejoin, cudaEventDisableTiming);
        init = true;
    }

    prep<<<10240, 256>>>(X, W);
    for (int k = 0; k < NCHUNKS; ++k) {
        dim3 g1(NPAD / BN, CROWS / BM);               // (32, 32)
        gemm_mma<<<g1, 256, SM_TOTAL>>>(b, s, k * CROWS);
        cudaEventRecord(eg[k], 0);
        cudaStreamWaitEvent(s2, eg[k], 0);
        tree_kernel<<<CROWS / 64, 512, 0, s2>>>(leaves, out, k * (CROWS / 2));
    }
    cudaEventRecord(ejoin, s2);
    cudaStreamWaitEvent(0, ejoin, 0);
}

// round 16
// speedup vs baseline: 1.6761x; 1.6761x over previous
#include <cuda_runtime.h>
#include <cuda_fp16.h>
#include <cstdint>

#define BATCH   16384
#define FEAT    512
#define NODES   4095
#define NPAD    4096
#define SPLIT   511            // nodes < SPLIT (levels 0-8) stored fp32

#define BM 128
#define BN 128
#define BKH 64                 // halves per k-stage (128B rows)
#define NKSTAGE (FEAT / BKH)   // 8
#define PSTAGES 3

// smem: A stages [0,48K), B stages [48K,96K), bias*scale 96K, scale 96K+512
#define SMA(s)   ((s) * 16384)
#define SMB(s)   (49152 + (s) * 16384)
#define SM_BS    98304
#define SM_SCALE 98816
#define SM_TOTAL 99328

__device__ float  g_P32[(size_t)512 * BATCH];        // levels 0-8  (nodes 0..510)
__device__ __half g_P16[(size_t)NPAD * BATCH];       // levels 9-11 (nodes 511..4094)
__device__ __half g_Xh[(size_t)BATCH * FEAT];
__device__ __half g_Wh[(size_t)NPAD * FEAT];         // row 4095 zeroed

// sigmoid via MUFU approx: rcp(1 + ex2(-x*log2e)); err ~2^-22
__device__ __forceinline__ float fast_sigmoid(float x) {
    float e, r;
    asm("ex2.approx.f32 %0, %1;" : "=f"(e) : "f"(-1.4426950408889634f * x));
    asm("rcp.approx.f32 %0, %1;" : "=f"(r) : "f"(1.0f + e));
    return r;
}
__device__ __forceinline__ uint32_t smem_u32(const void* p) {
    return (uint32_t)__cvta_generic_to_shared(p);
}
__device__ __forceinline__ void cp16(uint32_t dst, const void* src) {
    asm volatile("cp.async.cg.shared.global [%0], [%1], 16;" :: "r"(dst), "l"(src));
}
__device__ __forceinline__ void cp_commit() {
    asm volatile("cp.async.commit_group;" ::: "memory");
}
__device__ __forceinline__ void cp_wait1() {
    asm volatile("cp.async.wait_group 1;" ::: "memory");
}
__device__ __forceinline__ void ldsm4(uint32_t& r0, uint32_t& r1, uint32_t& r2,
                                      uint32_t& r3, uint32_t a) {
    asm volatile("ldmatrix.sync.aligned.m8n8.x4.shared.b16 {%0,%1,%2,%3}, [%4];"
                 : "=r"(r0), "=r"(r1), "=r"(r2), "=r"(r3) : "r"(a));
}
__device__ __forceinline__ void mma_f16(float* c, const uint32_t* a, const uint32_t* b) {
    asm volatile(
        "mma.sync.aligned.m16n8k16.row.col.f32.f16.f16.f32 "
        "{%0,%1,%2,%3}, {%4,%5,%6,%7}, {%8,%9}, {%0,%1,%2,%3};"
        : "+f"(c[0]), "+f"(c[1]), "+f"(c[2]), "+f"(c[3])
        : "r"(a[0]), "r"(a[1]), "r"(a[2]), "r"(a[3]), "r"(b[0]), "r"(b[1]));
}

// ---------------------------------------------------------------------------
// Fused prep: convert X [0,8192), W [8192,10240), zero out [10240,10304)
// ---------------------------------------------------------------------------
__global__ __launch_bounds__(256)
void prep(const float* __restrict__ X, const float* __restrict__ W,
          float* __restrict__ out)
{
    const int bid = blockIdx.x;
    if (bid < 8192) {
        size_t i = (size_t)bid * 256 + threadIdx.x;
        float4 v = ((const float4*)X)[i];
        __half2* d = (__half2*)g_Xh;
        d[2 * i]     = __floats2half2_rn(v.x, v.y);
        d[2 * i + 1] = __floats2half2_rn(v.z, v.w);
    } else if (bid < 10240) {
        size_t i = (size_t)(bid - 8192) * 256 + threadIdx.x;
        __half2* d = (__half2*)g_Wh;
        if (i < (size_t)NODES * FEAT / 4) {
            float4 v = ((const float4*)W)[i];
            d[2 * i]     = __floats2half2_rn(v.x, v.y);
            d[2 * i + 1] = __floats2half2_rn(v.z, v.w);
        } else {
            d[2 * i]     = __floats2half2_rn(0.f, 0.f);
            d[2 * i + 1] = __floats2half2_rn(0.f, 0.f);
        }
    } else {
        out[(bid - 10240) * 256 + threadIdx.x] = 0.f;
    }
}

// ---------------------------------------------------------------------------
// Kernel 1: fp16 mma.sync GEMM — R4/R10 config (measured best; ~87% of the
// legacy HMMA pipe ceiling per the R15 profile). Untouched.
// ---------------------------------------------------------------------------
__global__ __launch_bounds__(256, 2)
void gemm_mma(const float* __restrict__ bias, const float* __restrict__ scale)
{
    extern __shared__ char smem[];
    const uint32_t sbase = smem_u32(smem);

    const int tid  = threadIdx.x;
    const int lane = tid & 31;
    const int wid  = tid >> 5;
    const int warpM = wid & 1;          // 2 x 64 rows
    const int warpN = wid >> 1;         // 4 x 32 cols
    const int m0 = blockIdx.y * BM;
    const int n0 = blockIdx.x * BN;

    float* sbs = (float*)(smem + SM_BS);     // bias*scale
    float* ss  = (float*)(smem + SM_SCALE);  // scale
    if (tid < BN) {
        int nn = n0 + tid;
        bool v = nn < NODES;
        float bb = v ? bias[nn] : 0.f;
        float sc = v ? scale[nn] : 1.f;
        sbs[tid] = bb * sc;
        ss[tid]  = sc;
    }

    auto issue_stage = [&](int kt) {
        const int s = kt % PSTAGES;
        const int kb = kt * BKH;
        #pragma unroll
        for (int i = 0; i < 4; ++i) {
            int c = tid + i * 256;
            int row = c >> 3, chk = c & 7;
            uint32_t coff = (uint32_t)(chk * 16) ^ ((row & 7) << 4);
            cp16(sbase + SMA(s) + row * 128 + coff,
                 g_Xh + (size_t)(m0 + row) * FEAT + kb + chk * 8);
        }
        #pragma unroll
        for (int i = 0; i < 4; ++i) {
            int c = tid + i * 256;
            int row = c >> 3, chk = c & 7;
            uint32_t coff = (uint32_t)(chk * 16) ^ ((row & 7) << 4);
            cp16(sbase + SMB(s) + row * 128 + coff,
                 g_Wh + (size_t)(n0 + row) * FEAT + kb + chk * 8);
        }
        cp_commit();
    };

    float acc[4][4][4];
    #pragma unroll
    for (int f = 0; f < 4; f++)
        #pragma unroll
        for (int g = 0; g < 4; g++)
            #pragma unroll
            for (int j = 0; j < 4; j++)
                acc[f][g][j] = 0.f;

    issue_stage(0);
    issue_stage(1);

    const int q  = lane >> 3;
    const int lr = lane & 7;

    for (int kt = 0; kt < NKSTAGE; ++kt) {
        cp_wait1();
        __syncthreads();
        if (kt + 2 < NKSTAGE) issue_stage(kt + 2);
        else cp_commit();

        const uint32_t abase = sbase + SMA(kt % PSTAGES);
        const uint32_t bbase = sbase + SMB(kt % PSTAGES);

        #pragma unroll
        for (int g = 0; g < 4; ++g) {
            uint32_t af[4][4];
            #pragma unroll
            for (int t = 0; t < 4; ++t) {
                int trow = warpM * 64 + t * 16 + lr + (q & 1) * 8;
                uint32_t kbyte = (uint32_t)(g * 32 + (q >> 1) * 16);
                uint32_t addr = abase + trow * 128 + (kbyte ^ ((trow & 7) << 4));
                ldsm4(af[t][0], af[t][1], af[t][2], af[t][3], addr);
            }
            uint32_t bf[2][4];
            #pragma unroll
            for (int t = 0; t < 2; ++t) {
                int nrow = warpN * 32 + t * 16 + lr + (q >> 1) * 8;
                uint32_t kbyte = (uint32_t)(g * 32 + (q & 1) * 16);
                uint32_t addr = bbase + nrow * 128 + (kbyte ^ ((nrow & 7) << 4));
                ldsm4(bf[t][0], bf[t][1], bf[t][2], bf[t][3], addr);
            }
            #pragma unroll
            for (int f = 0; f < 4; ++f)
                #pragma unroll
                for (int gg = 0; gg < 4; ++gg) {
                    uint32_t bb[2] = { bf[gg >> 1][(gg & 1) * 2],
                                       bf[gg >> 1][(gg & 1) * 2 + 1] };
                    mma_f16(acc[f][gg], af[f], bb);
                }
        }
        __syncthreads();
    }

    // Epilogue: sigmoid(acc*s + b*s), direct hybrid stores
    const int rbase = m0 + warpM * 64 + (lane >> 2);
    #pragma unroll
    for (int f = 0; f < 4; ++f) {
        #pragma unroll
        for (int g = 0; g < 4; ++g) {
            const int cidx = warpN * 32 + g * 8 + (lane & 3) * 2;
            const int m = rbase + f * 16;
            #pragma unroll
            for (int j = 0; j < 4; ++j) {
                const int col = cidx + (j & 1);
                const int mm  = m + ((j >> 1) ? 8 : 0);
                const int node = n0 + col;
                float p = fast_sigmoid(fmaf(acc[f][g][j], ss[col], sbs[col]));
                if (node < SPLIT)
                    g_P32[(size_t)node * BATCH + mm] = p;
                else
                    g_P16[(size_t)node * BATCH + mm] = __float2half_rn(p);
            }
        }
    }
}

// ---------------------------------------------------------------------------
// Kernel 2: tree walk. grid (256, 2) x 512 thr. Keeps the measured-best
// 16 segs x 32 lanes shape; gridDim.y splits the 512 leaf-groups in half
// (16 groups/seg -> levels 0-4 + level-5 value hoisted). All 512 blocks fit
// in one wave (4/SM). Halves combine via atomicAdd onto zeroed out
// (2 commutative fp32 adds -> deterministic).
// ---------------------------------------------------------------------------
__global__ __launch_bounds__(512)
void tree_kernel(const float* __restrict__ leaves, float* __restrict__ out)
{
    __shared__ float sl[2048];
    __shared__ float2 part[16][33];
    const int tid = threadIdx.x;
    const int gbase = blockIdx.y * 256;       // this half's first leaf-group

    for (int i = tid; i < 2048; i += 512)
        sl[i] = fast_sigmoid(leaves[gbase * 8 + i]);
    __syncthreads();

    const int lane = tid & 31;
    const int seg  = tid >> 5;                // 0..15
    const int rh   = blockIdx.x * 32 + lane;  // row-pair index
    const float2*  __restrict__ PT2 = (const float2*)g_P32;
    const __half2* __restrict__ PH2 = (const __half2*)g_P16;
    const int HB = BATCH / 2;                 // 8192

    const int g0 = gbase + seg * 16;

    // hoist levels 0-4 (value+branch constant over the 16-group window)
    float prefA0 = 1.f, prefB0 = 1.f;
    #pragma unroll
    for (int d = 0; d < 5; ++d) {
        int idx = (1 << d) - 1 + (g0 >> (9 - d));
        float2 p = PT2[idx * HB + rh];
        int b = (g0 >> (8 - d)) & 1;
        prefA0 = b ? (prefA0 - prefA0 * p.x) : (prefA0 * p.x);
        prefB0 = b ? (prefB0 - prefB0 * p.y) : (prefB0 * p.y);
    }
    // level-5 value constant; branch bit (g>>3)&1 flips at gi=8
    const float2 p5 = PT2[(31 + (g0 >> 4)) * HB + rh];

    float accA = 0.f, accB = 0.f;
    #pragma unroll 2
    for (int gi = 0; gi < 16; ++gi) {
        const int g = g0 + gi;
        const int b5 = (g >> 3) & 1;
        float prefA = b5 ? (prefA0 - prefA0 * p5.x) : (prefA0 * p5.x);
        float prefB = b5 ? (prefB0 - prefB0 * p5.y) : (prefB0 * p5.y);
        #pragma unroll
        for (int d = 6; d < 9; ++d) {
            int idx = (1 << d) - 1 + (g >> (9 - d));
            float2 p = PT2[idx * HB + rh];
            int b = (g >> (8 - d)) & 1;
            prefA = b ? (prefA - prefA * p.x) : (prefA * p.x);
            prefB = b ? (prefB - prefB * p.y) : (prefB * p.y);
        }
        float2 p9  = __half22float2(PH2[(511  + g)     * HB + rh]);
        float2 pa0 = __half22float2(PH2[(1023 + 2 * g) * HB + rh]);
        float2 pa1 = __half22float2(PH2[(1024 + 2 * g) * HB + rh]);
        float2 pb0 = __half22float2(PH2[(2047 + 4 * g) * HB + rh]);
        float2 pb1 = __half22float2(PH2[(2048 + 4 * g) * HB + rh]);
        float2 pb2 = __half22float2(PH2[(2049 + 4 * g) * HB + rh]);
        float2 pb3 = __half22float2(PH2[(2050 + 4 * g) * HB + rh]);

        const float* s8 = &sl[(g - gbase) * 8];
        {
            float u0 = prefA * p9.x, u1 = prefA - u0;
            float v0 = u0 * pa0.x,   v1 = u0 - v0;
            float v2 = u1 * pa1.x,   v3 = u1 - v2;
            float w0 = v0 * pb0.x,   w1 = v0 - w0;
            float w2 = v1 * pb1.x,   w3 = v1 - w2;
            float w4 = v2 * pb2.x,   w5 = v2 - w4;
            float w6 = v3 * pb3.x,   w7 = v3 - w6;
            accA += s8[0] * w0 + s8[1] * w1 + s8[2] * w2 + s8[3] * w3
                  + s8[4] * w4 + s8[5] * w5 + s8[6] * w6 + s8[7] * w7;
        }
        {
            float u0 = prefB * p9.y, u1 = prefB - u0;
            float v0 = u0 * pa0.y,   v1 = u0 - v0;
            float v2 = u1 * pa1.y,   v3 = u1 - v2;
            float w0 = v0 * pb0.y,   w1 = v0 - w0;
            float w2 = v1 * pb1.y,   w3 = v1 - w2;
            float w4 = v2 * pb2.y,   w5 = v2 - w4;
            float w6 = v3 * pb3.y,   w7 = v3 - w6;
            accB += s8[0] * w0 + s8[1] * w1 + s8[2] * w2 + s8[3] * w3
                  + s8[4] * w4 + s8[5] * w5 + s8[6] * w6 + s8[7] * w7;
        }
    }
    part[seg][lane] = make_float2(accA, accB);
    __syncthreads();
    if (tid < 32) {
        float tA = 0.f, tB = 0.f;
        #pragma unroll
        for (int s2 = 0; s2 < 16; ++s2) {
            float2 v = part[s2][tid];
            tA += v.x; tB += v.y;
        }
        const int r = blockIdx.x * 32 + tid;
        atomicAdd(&out[r * 2],     tA);
        atomicAdd(&out[r * 2 + 1], tB);
    }
}

// ---------------------------------------------------------------------------
extern "C" void kernel_launch(void* const* d_in, const int* in_sizes, int n_in,
                              void* d_out, int out_size)
{
    const float* X      = (const float*)d_in[0];
    const float* W      = (const float*)d_in[1];
    const float* b      = (const float*)d_in[2];
    const float* s      = (const float*)d_in[3];
    const float* leaves = (const float*)d_in[4];
    float* out = (float*)d_out;

    static bool attr_set = false;
    if (!attr_set) {
        cudaFuncSetAttribute(gemm_mma, cudaFuncAttributeMaxDynamicSharedMemorySize,
                             SM_TOTAL);
        attr_set = true;
    }

    prep<<<10304, 256>>>(X, W, out);              // convX + convW + zero out
    dim3 g1(NPAD / BN, BATCH / BM);               // (32, 128)
    gemm_mma<<<g1, 256, SM_TOTAL>>>(b, s);
    dim3 g2(256, 2);
    tree_kernel<<<g2, 512>>>(leaves, out);
}